// round 2
// baseline (speedup 1.0000x reference)
#include <cuda_runtime.h>
#include <math.h>

#define S_LEN    2048
#define DIM      3072
#define HEADS    24
#define HEAD_DIM 128

// Scratch (no cudaMalloc allowed): q, k, v post-projection
__device__ float g_q[S_LEN * DIM];
__device__ float g_k[S_LEN * DIM];
__device__ float g_v[S_LEN * DIM];

typedef unsigned long long ull;

// ---- packed fp32x2 helpers (Blackwell f32x2 pipe; ptxas never emits these) ----
__device__ __forceinline__ ull ffma2(ull a, ull b, ull c) {
    ull d;
    asm("fma.rn.f32x2 %0, %1, %2, %3;" : "=l"(d) : "l"(a), "l"(b), "l"(c));
    return d;
}
__device__ __forceinline__ ull fmul2(ull a, ull b) {
    ull d;
    asm("mul.rn.f32x2 %0, %1, %2;" : "=l"(d) : "l"(a), "l"(b));
    return d;
}
__device__ __forceinline__ ull pack2(float lo, float hi) {
    ull r;
    asm("mov.b64 %0, {%1, %2};" : "=l"(r) : "f"(lo), "f"(hi));
    return r;
}
__device__ __forceinline__ float2 unpack2f(ull v) {
    float lo, hi;
    asm("mov.b64 {%0, %1}, %2;" : "=f"(lo), "=f"(hi) : "l"(v));
    return make_float2(lo, hi);
}

// ---------------------------------------------------------------------------
// Stage 1: QKV projection. C = x @ W + b for W in {Wq, Wk, Wv} (blockIdx.z).
// 128x128x8 tile, 256 threads, 8x8 microtile computed as 8x4 packed f32x2.
// A stored in smem pre-duplicated (a,a) as u64 -> zero packing in hot loop.
// Double-buffered smem, one __syncthreads per k-step.
// ---------------------------------------------------------------------------
#define BM 128
#define BN 128
#define BK 8

__global__ __launch_bounds__(256, 2) void qkv_gemm_kernel(
    const float* __restrict__ x,
    const float* __restrict__ Wq, const float* __restrict__ bq,
    const float* __restrict__ Wk, const float* __restrict__ bk,
    const float* __restrict__ Wv, const float* __restrict__ bv)
{
    const float* W; const float* bias; float* out;
    if (blockIdx.z == 0)      { W = Wq; bias = bq; out = g_q; }
    else if (blockIdx.z == 1) { W = Wk; bias = bk; out = g_k; }
    else                      { W = Wv; bias = bv; out = g_v; }

    __shared__ ull   As[2][BK][BM];   // duplicated pack: As[k][m] = (a,a)
    __shared__ float Bs[2][BK][BN];

    const int tid  = threadIdx.x;
    const int row0 = blockIdx.y * BM;
    const int col0 = blockIdx.x * BN;

    const int trow = (tid / 16) * 8;
    const int tcol = (tid % 16) * 8;

    ull acc[8][4];
    #pragma unroll
    for (int i = 0; i < 8; i++)
        #pragma unroll
        for (int j = 0; j < 4; j++) acc[i][j] = 0ULL;

    const int arow = tid >> 1;          // 0..127
    const int acol = (tid & 1) * 4;     // 0 or 4
    const int brow = tid >> 5;          // 0..7
    const int bcol = (tid & 31) * 4;    // 0..124

    const float* xA = x + (size_t)(row0 + arow) * DIM + acol;
    const float* wB = W + (size_t)brow * DIM + col0 + bcol;

    // prime buffer 0
    {
        float4 av = *(const float4*)(xA);
        float4 bv = *(const float4*)(wB);
        As[0][acol + 0][arow] = pack2(av.x, av.x);
        As[0][acol + 1][arow] = pack2(av.y, av.y);
        As[0][acol + 2][arow] = pack2(av.z, av.z);
        As[0][acol + 3][arow] = pack2(av.w, av.w);
        *(float4*)(&Bs[0][brow][bcol]) = bv;
    }

    int buf = 0;
    for (int k0 = 0; k0 < DIM; k0 += BK) {
        __syncthreads();

        const bool has_next = (k0 + BK) < DIM;
        float4 av, bv;
        if (has_next) {
            av = *(const float4*)(xA + k0 + BK);
            bv = *(const float4*)(wB + (size_t)(k0 + BK) * DIM);
        }

        #pragma unroll
        for (int kk = 0; kk < BK; kk++) {
            const ulonglong2* Ad = (const ulonglong2*)&As[buf][kk][trow];
            const ulonglong2* Bd = (const ulonglong2*)&Bs[buf][kk][tcol];
            ulonglong2 a01 = Ad[0], a23 = Ad[1], a45 = Ad[2], a67 = Ad[3];
            ulonglong2 bd0 = Bd[0], bd1 = Bd[1];
            ull af[8] = {a01.x, a01.y, a23.x, a23.y, a45.x, a45.y, a67.x, a67.y};
            ull bf[4] = {bd0.x, bd0.y, bd1.x, bd1.y};
            #pragma unroll
            for (int i = 0; i < 8; i++)
                #pragma unroll
                for (int j = 0; j < 4; j++)
                    acc[i][j] = ffma2(af[i], bf[j], acc[i][j]);
        }

        if (has_next) {
            const int nb = buf ^ 1;
            As[nb][acol + 0][arow] = pack2(av.x, av.x);
            As[nb][acol + 1][arow] = pack2(av.y, av.y);
            As[nb][acol + 2][arow] = pack2(av.z, av.z);
            As[nb][acol + 3][arow] = pack2(av.w, av.w);
            *(float4*)(&Bs[nb][brow][bcol]) = bv;
        }
        buf ^= 1;
    }

    const float4 bia0 = *(const float4*)(bias + col0 + tcol);
    const float4 bia1 = *(const float4*)(bias + col0 + tcol + 4);

    #pragma unroll
    for (int i = 0; i < 8; i++) {
        float2 c0 = unpack2f(acc[i][0]);
        float2 c1 = unpack2f(acc[i][1]);
        float2 c2 = unpack2f(acc[i][2]);
        float2 c3 = unpack2f(acc[i][3]);
        float4 o0 = make_float4(c0.x + bia0.x, c0.y + bia0.y, c1.x + bia0.z, c1.y + bia0.w);
        float4 o1 = make_float4(c2.x + bia1.x, c2.y + bia1.y, c3.x + bia1.z, c3.y + bia1.w);
        float* dst = out + (size_t)(row0 + trow + i) * DIM + col0 + tcol;
        *(float4*)(dst)     = o0;
        *(float4*)(dst + 4) = o1;
    }
}

// ---------------------------------------------------------------------------
// Stage 2: per-head RMSNorm + RoPE applied in place to g_q and g_k.
// One warp per (tensor, seq, head) row of 128.
// ---------------------------------------------------------------------------
__global__ __launch_bounds__(256) void rms_rope_kernel(
    const float* __restrict__ cosb, const float* __restrict__ sinb,
    const float* __restrict__ gq, const float* __restrict__ gk)
{
    const int gw   = (blockIdx.x * blockDim.x + threadIdx.x) >> 5;
    const int lane = threadIdx.x & 31;
    const int rows = S_LEN * HEADS;
    if (gw >= 2 * rows) return;

    const int t  = (gw >= rows) ? 1 : 0;
    const int rr = t ? (gw - rows) : gw;
    const int s  = rr / HEADS;

    float* ptr = (t ? g_k : g_q) + (size_t)rr * HEAD_DIM;
    const float* g = t ? gk : gq;

    float4 vx = *(float4*)(ptr + lane * 4);
    float ss = vx.x * vx.x + vx.y * vx.y + vx.z * vx.z + vx.w * vx.w;
    #pragma unroll
    for (int o = 16; o > 0; o >>= 1) ss += __shfl_xor_sync(0xffffffffu, ss, o);
    const float rnorm = rsqrtf(ss * (1.0f / HEAD_DIM) + 1e-6f);

    float4 gg = *(const float4*)(g + lane * 4);
    vx.x *= rnorm * gg.x; vx.y *= rnorm * gg.y;
    vx.z *= rnorm * gg.z; vx.w *= rnorm * gg.w;

    float4 c  = *(const float4*)(cosb + (size_t)s * HEAD_DIM + lane * 4);
    float4 sn = *(const float4*)(sinb + (size_t)s * HEAD_DIM + lane * 4);
    float4 o;
    o.x = vx.x * c.x - vx.y * sn.x;
    o.y = vx.y * c.y + vx.x * sn.y;
    o.z = vx.z * c.z - vx.w * sn.z;
    o.w = vx.w * c.w + vx.z * sn.w;
    *(float4*)(ptr + lane * 4) = o;
}

// ---------------------------------------------------------------------------
// Stage 3: flash attention, fp32 with packed f32x2 FMAs.
// 64 q-rows x 64 kv-rows per tile; 8 warps; warp w owns q-rows [8w, 8w+8).
// S accumulates packed-along-d (horizontal add at end). P stored in smem
// pre-duplicated (p,p) as u64 -> pack-free PV loop.
// ---------------------------------------------------------------------------
#define BQ  64
#define BKV 64
#define ATTN_THREADS 256
// floats: Qs 64*128 + Kt 32*65*4 + Vs 64*128 + Ps(u64) 64*64*2
#define ATTN_SMEM_FLOATS (64*128 + 32*65*4 + 64*128 + 64*64*2)
#define ATTN_SMEM_BYTES  (ATTN_SMEM_FLOATS * 4)

__global__ __launch_bounds__(ATTN_THREADS) void attn_kernel(float* __restrict__ out)
{
    extern __shared__ float sm[];
    float* Qs = sm;                         // [64][128] floats
    float* Kt = Qs + 64 * 128;              // float4 grid [32][65] (d4-major)
    float* Vs = Kt + 32 * 65 * 4;           // [64][128] floats
    ull*   Ps = (ull*)(Vs + 64 * 128);      // [64][64] duplicated-pack u64

    const int h    = blockIdx.y;
    const int q0   = blockIdx.x * BQ;
    const int tid  = threadIdx.x;
    const int warp = tid >> 5;
    const int lane = tid & 31;

    const float scale = 0.08838834764831845f;   // 1/sqrt(128)

    // Load Q tile, pre-scaled
    for (int i = tid; i < BQ * HEAD_DIM / 4; i += ATTN_THREADS) {
        const int r  = i >> 5;
        const int c4 = i & 31;
        float4 val = *(const float4*)(g_q + ((size_t)(q0 + r) * HEADS + h) * HEAD_DIM + c4 * 4);
        val.x *= scale; val.y *= scale; val.z *= scale; val.w *= scale;
        ((float4*)Qs)[i] = val;
    }

    ull   ax[8], ay[8];
    float m_i[8], l_i[8];
    #pragma unroll
    for (int r = 0; r < 8; r++) {
        ax[r] = 0ULL; ay[r] = 0ULL;
        m_i[r] = -INFINITY;
        l_i[r] = 0.f;
    }

    for (int kv0 = 0; kv0 < S_LEN; kv0 += BKV) {
        __syncthreads();   // previous tile's smem fully consumed
        // K tile: float4 over d per kk; store at [d4][kk], row stride 65
        for (int i = tid; i < BKV * HEAD_DIM / 4; i += ATTN_THREADS) {
            const int kk = i >> 5;
            const int d4 = i & 31;
            float4 val = *(const float4*)(g_k + ((size_t)(kv0 + kk) * HEADS + h) * HEAD_DIM + d4 * 4);
            ((float4*)Kt)[d4 * 65 + kk] = val;
        }
        // V tile: row-major [kk][d]
        for (int i = tid; i < BKV * HEAD_DIM / 4; i += ATTN_THREADS) {
            ((float4*)Vs)[i] =
                *(const float4*)(g_v + ((size_t)(kv0 + (i >> 5)) * HEADS + h) * HEAD_DIM + (i & 31) * 4);
        }
        __syncthreads();

        // ---- S = Q K^T, packed along d. lane -> k cols {lane, lane+32} ----
        ull s0p[8], s1p[8];
        #pragma unroll
        for (int r = 0; r < 8; r++) { s0p[r] = 0ULL; s1p[r] = 0ULL; }
        const ulonglong2* Qd = (const ulonglong2*)Qs + (size_t)(warp * 8) * 32;
        const ulonglong2* Kd = (const ulonglong2*)Kt;
        #pragma unroll 4
        for (int d4 = 0; d4 < 32; d4++) {
            const ulonglong2 k0v = Kd[d4 * 65 + lane];
            const ulonglong2 k1v = Kd[d4 * 65 + lane + 32];
            #pragma unroll
            for (int r = 0; r < 8; r++) {
                const ulonglong2 qv = Qd[r * 32 + d4];
                s0p[r] = ffma2(qv.x, k0v.x, s0p[r]);
                s0p[r] = ffma2(qv.y, k0v.y, s0p[r]);
                s1p[r] = ffma2(qv.x, k1v.x, s1p[r]);
                s1p[r] = ffma2(qv.y, k1v.y, s1p[r]);
            }
        }

        // ---- online softmax; stage duplicated-pack P into smem ----
        #pragma unroll
        for (int r = 0; r < 8; r++) {
            float2 t0 = unpack2f(s0p[r]);
            float2 t1 = unpack2f(s1p[r]);
            const float s0 = t0.x + t0.y;
            const float s1 = t1.x + t1.y;
            float mx = fmaxf(s0, s1);
            #pragma unroll
            for (int o = 16; o > 0; o >>= 1) mx = fmaxf(mx, __shfl_xor_sync(0xffffffffu, mx, o));
            const float m_new = fmaxf(m_i[r], mx);
            const float alpha = __expf(m_i[r] - m_new);
            const float p0 = __expf(s0 - m_new);
            const float p1 = __expf(s1 - m_new);
            float ps = p0 + p1;
            #pragma unroll
            for (int o = 16; o > 0; o >>= 1) ps += __shfl_xor_sync(0xffffffffu, ps, o);
            l_i[r] = l_i[r] * alpha + ps;
            m_i[r] = m_new;
            const ull aa = pack2(alpha, alpha);
            ax[r] = fmul2(ax[r], aa);
            ay[r] = fmul2(ay[r], aa);
            Ps[(warp * 8 + r) * 64 + lane]      = pack2(p0, p0);
            Ps[(warp * 8 + r) * 64 + lane + 32] = pack2(p1, p1);
        }
        __syncwarp();

        // ---- O += P V (lane owns output cols 4*lane..4*lane+3) ----
        const ulonglong2* Pd = (const ulonglong2*)Ps + (size_t)(warp * 8) * 32;
        const ulonglong2* Vd = (const ulonglong2*)Vs;
        #pragma unroll 4
        for (int kk2 = 0; kk2 < 32; kk2++) {
            const ulonglong2 vv0 = Vd[(2 * kk2)     * 32 + lane];
            const ulonglong2 vv1 = Vd[(2 * kk2 + 1) * 32 + lane];
            #pragma unroll
            for (int r = 0; r < 8; r++) {
                const ulonglong2 pd = Pd[r * 32 + kk2];
                ax[r] = ffma2(pd.x, vv0.x, ax[r]);
                ay[r] = ffma2(pd.x, vv0.y, ay[r]);
                ax[r] = ffma2(pd.y, vv1.x, ax[r]);
                ay[r] = ffma2(pd.y, vv1.y, ay[r]);
            }
        }
    }

    // epilogue: normalize and store out[b, q, h*128 + c]
    #pragma unroll
    for (int r = 0; r < 8; r++) {
        const float inv = 1.f / l_i[r];
        float2 x01 = unpack2f(ax[r]);
        float2 x23 = unpack2f(ay[r]);
        float4 o = make_float4(x01.x * inv, x01.y * inv, x23.x * inv, x23.y * inv);
        const int row = q0 + warp * 8 + r;
        *(float4*)(out + (size_t)row * DIM + h * HEAD_DIM + lane * 4) = o;
    }
}

// ---------------------------------------------------------------------------
extern "C" void kernel_launch(void* const* d_in, const int* in_sizes, int n_in,
                              void* d_out, int out_size)
{
    (void)in_sizes; (void)n_in; (void)out_size;
    const float* x  = (const float*)d_in[0];
    const float* cs = (const float*)d_in[1];
    const float* sn = (const float*)d_in[2];
    const float* Wq = (const float*)d_in[3];
    const float* bq = (const float*)d_in[4];
    const float* Wk = (const float*)d_in[5];
    const float* bk = (const float*)d_in[6];
    const float* Wv = (const float*)d_in[7];
    const float* bv = (const float*)d_in[8];
    const float* gq = (const float*)d_in[9];
    const float* gk = (const float*)d_in[10];
    float* out = (float*)d_out;

    // Stage 1: QKV projections
    dim3 gg(DIM / BN, S_LEN / BM, 3);
    qkv_gemm_kernel<<<gg, 256>>>(x, Wq, bq, Wk, bk, Wv, bv);

    // Stage 2: RMSNorm + RoPE on q, k
    const int warps  = 2 * S_LEN * HEADS;
    const int thr    = 256;
    const int blocks = (warps * 32 + thr - 1) / thr;
    rms_rope_kernel<<<blocks, thr>>>(cs, sn, gq, gk);

    // Stage 3: attention
    cudaFuncSetAttribute(attn_kernel, cudaFuncAttributeMaxDynamicSharedMemorySize,
                         ATTN_SMEM_BYTES);
    dim3 ga(S_LEN / BQ, HEADS);
    attn_kernel<<<ga, ATTN_THREADS, ATTN_SMEM_BYTES>>>(out);
}

// round 6
// speedup vs baseline: 1.4863x; 1.4863x over previous
#include <cuda_runtime.h>
#include <math.h>
#include <stdint.h>

#define S_LEN    2048
#define DIM      3072
#define HEADS    24
#define HEAD_DIM 128

// Scratch (no cudaMalloc allowed): q, k, v post-projection
__device__ float g_q[S_LEN * DIM];
__device__ float g_k[S_LEN * DIM];
__device__ float g_v[S_LEN * DIM];

// ---- helpers -------------------------------------------------------------
__device__ __forceinline__ uint32_t tf32_rna(float x) {
    uint32_t r;
    asm("cvt.rna.tf32.f32 %0, %1;" : "=r"(r) : "f"(x));
    return r;
}
__device__ __forceinline__ void mma_tf32(float c[4], const uint32_t a[4], const uint32_t b[2]) {
    asm volatile(
        "mma.sync.aligned.m16n8k8.row.col.f32.tf32.tf32.f32 "
        "{%0,%1,%2,%3}, {%4,%5,%6,%7}, {%8,%9}, {%0,%1,%2,%3};"
        : "+f"(c[0]), "+f"(c[1]), "+f"(c[2]), "+f"(c[3])
        : "r"(a[0]), "r"(a[1]), "r"(a[2]), "r"(a[3]), "r"(b[0]), "r"(b[1]));
}

// ===========================================================================
// Stage 1: QKV projection via mma.sync tf32 (A = hi+lo split, B = tf32-rna).
// CTA tile 128x128, K-chunk 32, double-buffered smem, 8 warps (2m x 4n),
// warp tile 64x32 (4 m-tiles x 4 n-tiles of m16n8k8).
// Smem strides: A 36 floats (bank (4g+t) bijective), B 136 ((8t+g) bijective).
// ===========================================================================
#define QA_STRIDE 36
#define QB_STRIDE 136
#define QA_FLOATS (128 * QA_STRIDE)            // 4608
#define QB_FLOATS (32 * QB_STRIDE)             // 4352
#define QBUF_FLOATS (2 * QA_FLOATS + QB_FLOATS)  // 13568
#define QSMEM_BYTES (2 * QBUF_FLOATS * 4)        // 108544
#define NCHUNK (DIM / 32)                        // 96

__global__ __launch_bounds__(256, 1) void qkv_mma_kernel(
    const float* __restrict__ x,
    const float* __restrict__ Wq, const float* __restrict__ bq,
    const float* __restrict__ Wk, const float* __restrict__ bk,
    const float* __restrict__ Wv, const float* __restrict__ bv)
{
    extern __shared__ float smem[];
    const float* W; const float* bias; float* out;
    if (blockIdx.z == 0)      { W = Wq; bias = bq; out = g_q; }
    else if (blockIdx.z == 1) { W = Wk; bias = bk; out = g_k; }
    else                      { W = Wv; bias = bv; out = g_v; }

    const int tid  = threadIdx.x;
    const int wid  = tid >> 5;
    const int lane = tid & 31;
    const int g    = lane >> 2;      // group id 0..7
    const int tg   = lane & 3;       // thread-in-group 0..3
    const int wm   = wid >> 2;       // 0..1 -> m offset 64*wm
    const int wn   = wid & 3;        // 0..3 -> n offset 32*wn
    const int row0 = blockIdx.y * 128;
    const int col0 = blockIdx.x * 128;

    // fill indices
    const int arow = tid >> 1;              // 0..127
    const int acol = (tid & 1) * 16;        // 0/16
    const int brow = tid >> 3;              // 0..31
    const int bcol = (tid & 7) * 16;        // 0..112

    const float* xA = x + (size_t)(row0 + arow) * DIM + acol;
    const float* wB = W + (size_t)brow * DIM + col0 + bcol;

    float acc[4][4][4];
    #pragma unroll
    for (int i = 0; i < 4; i++)
        #pragma unroll
        for (int j = 0; j < 4; j++)
            #pragma unroll
            for (int r = 0; r < 4; r++) acc[i][j][r] = 0.f;

    // buffer pointers
    auto As_h = [&](int b) { return smem + (size_t)b * QBUF_FLOATS; };
    auto As_l = [&](int b) { return smem + (size_t)b * QBUF_FLOATS + QA_FLOATS; };
    auto Bs   = [&](int b) { return smem + (size_t)b * QBUF_FLOATS + 2 * QA_FLOATS; };

    // ---- prime chunk 0 into buffer 0 ----
    {
        #pragma unroll
        for (int j = 0; j < 4; j++) {
            float4 v = *(const float4*)(xA + j * 4);
            uint4 h, l;
            h.x = tf32_rna(v.x); l.x = tf32_rna(v.x - __uint_as_float(h.x));
            h.y = tf32_rna(v.y); l.y = tf32_rna(v.y - __uint_as_float(h.y));
            h.z = tf32_rna(v.z); l.z = tf32_rna(v.z - __uint_as_float(h.z));
            h.w = tf32_rna(v.w); l.w = tf32_rna(v.w - __uint_as_float(h.w));
            *(uint4*)(As_h(0) + arow * QA_STRIDE + acol + j * 4) = h;
            *(uint4*)(As_l(0) + arow * QA_STRIDE + acol + j * 4) = l;
        }
        #pragma unroll
        for (int j = 0; j < 4; j++) {
            float4 v = *(const float4*)(wB + j * 4);
            uint4 h;
            h.x = tf32_rna(v.x); h.y = tf32_rna(v.y);
            h.z = tf32_rna(v.z); h.w = tf32_rna(v.w);
            *(uint4*)(Bs(0) + brow * QB_STRIDE + bcol + j * 4) = h;
        }
    }

    for (int c = 0; c < NCHUNK; c++) {
        __syncthreads();
        const int b = c & 1;
        const bool has_next = (c + 1) < NCHUNK;

        float4 av[4], bv[4];
        if (has_next) {
            const int kn = (c + 1) * 32;
            #pragma unroll
            for (int j = 0; j < 4; j++) av[j] = *(const float4*)(xA + kn + j * 4);
            #pragma unroll
            for (int j = 0; j < 4; j++) bv[j] = *(const float4*)(wB + (size_t)kn * DIM + j * 4);
        }

        // ---- compute chunk c from buffer b ----
        const uint32_t* Ah = (const uint32_t*)As_h(b);
        const uint32_t* Al = (const uint32_t*)As_l(b);
        const uint32_t* Bp = (const uint32_t*)Bs(b);
        #pragma unroll
        for (int kk8 = 0; kk8 < 4; kk8++) {
            const int kk = kk8 * 8;
            uint32_t ah[4][4], al[4][4], bb[4][2];
            #pragma unroll
            for (int i = 0; i < 4; i++) {
                const int r = wm * 64 + i * 16 + g;
                ah[i][0] = Ah[(r)     * QA_STRIDE + kk + tg];
                ah[i][1] = Ah[(r + 8) * QA_STRIDE + kk + tg];
                ah[i][2] = Ah[(r)     * QA_STRIDE + kk + tg + 4];
                ah[i][3] = Ah[(r + 8) * QA_STRIDE + kk + tg + 4];
                al[i][0] = Al[(r)     * QA_STRIDE + kk + tg];
                al[i][1] = Al[(r + 8) * QA_STRIDE + kk + tg];
                al[i][2] = Al[(r)     * QA_STRIDE + kk + tg + 4];
                al[i][3] = Al[(r + 8) * QA_STRIDE + kk + tg + 4];
            }
            #pragma unroll
            for (int j = 0; j < 4; j++) {
                const int n = wn * 32 + j * 8 + g;
                bb[j][0] = Bp[(kk + tg)     * QB_STRIDE + n];
                bb[j][1] = Bp[(kk + tg + 4) * QB_STRIDE + n];
            }
            #pragma unroll
            for (int i = 0; i < 4; i++)
                #pragma unroll
                for (int j = 0; j < 4; j++) {
                    mma_tf32(acc[i][j], ah[i], bb[j]);
                    mma_tf32(acc[i][j], al[i], bb[j]);
                }
        }

        // ---- store chunk c+1 into buffer b^1 ----
        if (has_next) {
            const int nb = b ^ 1;
            #pragma unroll
            for (int j = 0; j < 4; j++) {
                uint4 h, l;
                h.x = tf32_rna(av[j].x); l.x = tf32_rna(av[j].x - __uint_as_float(h.x));
                h.y = tf32_rna(av[j].y); l.y = tf32_rna(av[j].y - __uint_as_float(h.y));
                h.z = tf32_rna(av[j].z); l.z = tf32_rna(av[j].z - __uint_as_float(h.z));
                h.w = tf32_rna(av[j].w); l.w = tf32_rna(av[j].w - __uint_as_float(h.w));
                *(uint4*)(As_h(nb) + arow * QA_STRIDE + acol + j * 4) = h;
                *(uint4*)(As_l(nb) + arow * QA_STRIDE + acol + j * 4) = l;
            }
            #pragma unroll
            for (int j = 0; j < 4; j++) {
                uint4 h;
                h.x = tf32_rna(bv[j].x); h.y = tf32_rna(bv[j].y);
                h.z = tf32_rna(bv[j].z); h.w = tf32_rna(bv[j].w);
                *(uint4*)(Bs(nb) + brow * QB_STRIDE + bcol + j * 4) = h;
            }
        }
    }

    // ---- epilogue: add bias, store ----
    #pragma unroll
    for (int j = 0; j < 4; j++) {
        const int n = col0 + wn * 32 + j * 8 + 2 * tg;
        const float2 bb = *(const float2*)(bias + n);
        #pragma unroll
        for (int i = 0; i < 4; i++) {
            const int r = row0 + wm * 64 + i * 16 + g;
            float2 o0 = make_float2(acc[i][j][0] + bb.x, acc[i][j][1] + bb.y);
            float2 o1 = make_float2(acc[i][j][2] + bb.x, acc[i][j][3] + bb.y);
            *(float2*)(out + (size_t)r * DIM + n)       = o0;
            *(float2*)(out + (size_t)(r + 8) * DIM + n) = o1;
        }
    }
}

// ---------------------------------------------------------------------------
// Stage 2: per-head RMSNorm + RoPE applied in place to g_q and g_k.
// ---------------------------------------------------------------------------
__global__ __launch_bounds__(256) void rms_rope_kernel(
    const float* __restrict__ cosb, const float* __restrict__ sinb,
    const float* __restrict__ gq, const float* __restrict__ gk)
{
    const int gw   = (blockIdx.x * blockDim.x + threadIdx.x) >> 5;
    const int lane = threadIdx.x & 31;
    const int rows = S_LEN * HEADS;
    if (gw >= 2 * rows) return;

    const int t  = (gw >= rows) ? 1 : 0;
    const int rr = t ? (gw - rows) : gw;
    const int s  = rr / HEADS;

    float* ptr = (t ? g_k : g_q) + (size_t)rr * HEAD_DIM;
    const float* g = t ? gk : gq;

    float4 vx = *(float4*)(ptr + lane * 4);
    float ss = vx.x * vx.x + vx.y * vx.y + vx.z * vx.z + vx.w * vx.w;
    #pragma unroll
    for (int o = 16; o > 0; o >>= 1) ss += __shfl_xor_sync(0xffffffffu, ss, o);
    const float rnorm = rsqrtf(ss * (1.0f / HEAD_DIM) + 1e-6f);

    float4 gg = *(const float4*)(g + lane * 4);
    vx.x *= rnorm * gg.x; vx.y *= rnorm * gg.y;
    vx.z *= rnorm * gg.z; vx.w *= rnorm * gg.w;

    float4 c  = *(const float4*)(cosb + (size_t)s * HEAD_DIM + lane * 4);
    float4 sn = *(const float4*)(sinb + (size_t)s * HEAD_DIM + lane * 4);
    float4 o;
    o.x = vx.x * c.x - vx.y * sn.x;
    o.y = vx.y * c.y + vx.x * sn.y;
    o.z = vx.z * c.z - vx.w * sn.z;
    o.w = vx.w * c.w + vx.z * sn.w;
    *(float4*)(ptr + lane * 4) = o;
}

// ---------------------------------------------------------------------------
// Stage 3: flash attention, fp32 (round-1 proven version).
// ---------------------------------------------------------------------------
#define BQ  64
#define BKV 64
#define ATTN_THREADS 256
#define ATTN_SMEM_FLOATS (64*128 + 32*65*4 + 64*128 + 64*64)
#define ATTN_SMEM_BYTES  (ATTN_SMEM_FLOATS * 4)

__global__ __launch_bounds__(ATTN_THREADS) void attn_kernel(float* __restrict__ out)
{
    extern __shared__ float sm[];
    float* Qs = sm;                         // [64][128]
    float* Kt = Qs + 64 * 128;              // float4 grid [32][65]
    float* Vs = Kt + 32 * 65 * 4;           // [64][128]
    float* Ps = Vs + 64 * 128;              // [64][64]

    const int h    = blockIdx.y;
    const int q0   = blockIdx.x * BQ;
    const int tid  = threadIdx.x;
    const int warp = tid >> 5;
    const int lane = tid & 31;

    const float scale = 0.08838834764831845f;

    for (int i = tid; i < BQ * HEAD_DIM / 4; i += ATTN_THREADS) {
        const int r  = i >> 5;
        const int c4 = i & 31;
        float4 val = *(const float4*)(g_q + ((size_t)(q0 + r) * HEADS + h) * HEAD_DIM + c4 * 4);
        val.x *= scale; val.y *= scale; val.z *= scale; val.w *= scale;
        ((float4*)Qs)[i] = val;
    }

    float4 acc[8];
    float  m_i[8], l_i[8];
    #pragma unroll
    for (int r = 0; r < 8; r++) {
        acc[r] = make_float4(0.f, 0.f, 0.f, 0.f);
        m_i[r] = -INFINITY;
        l_i[r] = 0.f;
    }

    for (int kv0 = 0; kv0 < S_LEN; kv0 += BKV) {
        __syncthreads();
        for (int i = tid; i < BKV * HEAD_DIM / 4; i += ATTN_THREADS) {
            const int kk = i >> 5;
            const int d4 = i & 31;
            float4 val = *(const float4*)(g_k + ((size_t)(kv0 + kk) * HEADS + h) * HEAD_DIM + d4 * 4);
            ((float4*)Kt)[d4 * 65 + kk] = val;
        }
        for (int i = tid; i < BKV * HEAD_DIM / 4; i += ATTN_THREADS) {
            ((float4*)Vs)[i] =
                *(const float4*)(g_v + ((size_t)(kv0 + (i >> 5)) * HEADS + h) * HEAD_DIM + (i & 31) * 4);
        }
        __syncthreads();

        float s0[8], s1[8];
        #pragma unroll
        for (int r = 0; r < 8; r++) { s0[r] = 0.f; s1[r] = 0.f; }
        const float4* Qs4 = (const float4*)Qs + (size_t)(warp * 8) * 32;
        const float4* Kt4 = (const float4*)Kt;
        #pragma unroll 4
        for (int d4 = 0; d4 < 32; d4++) {
            const float4 kb0 = Kt4[d4 * 65 + lane];
            const float4 kb1 = Kt4[d4 * 65 + lane + 32];
            #pragma unroll
            for (int r = 0; r < 8; r++) {
                const float4 qv = Qs4[r * 32 + d4];
                s0[r] += qv.x * kb0.x + qv.y * kb0.y + qv.z * kb0.z + qv.w * kb0.w;
                s1[r] += qv.x * kb1.x + qv.y * kb1.y + qv.z * kb1.z + qv.w * kb1.w;
            }
        }

        #pragma unroll
        for (int r = 0; r < 8; r++) {
            float mx = fmaxf(s0[r], s1[r]);
            #pragma unroll
            for (int o = 16; o > 0; o >>= 1) mx = fmaxf(mx, __shfl_xor_sync(0xffffffffu, mx, o));
            const float m_new = fmaxf(m_i[r], mx);
            const float alpha = __expf(m_i[r] - m_new);
            const float p0 = __expf(s0[r] - m_new);
            const float p1 = __expf(s1[r] - m_new);
            float ps = p0 + p1;
            #pragma unroll
            for (int o = 16; o > 0; o >>= 1) ps += __shfl_xor_sync(0xffffffffu, ps, o);
            l_i[r] = l_i[r] * alpha + ps;
            m_i[r] = m_new;
            acc[r].x *= alpha; acc[r].y *= alpha; acc[r].z *= alpha; acc[r].w *= alpha;
            Ps[(warp * 8 + r) * 64 + lane]      = p0;
            Ps[(warp * 8 + r) * 64 + lane + 32] = p1;
        }
        __syncwarp();

        const float4* Ps4 = (const float4*)Ps + (size_t)(warp * 8) * 16;
        const float4* Vs4 = (const float4*)Vs;
        #pragma unroll 4
        for (int kk4 = 0; kk4 < 16; kk4++) {
            float4 pv[8];
            #pragma unroll
            for (int r = 0; r < 8; r++) pv[r] = Ps4[r * 16 + kk4];
            #pragma unroll
            for (int u = 0; u < 4; u++) {
                const float4 vv = Vs4[(kk4 * 4 + u) * 32 + lane];
                #pragma unroll
                for (int r = 0; r < 8; r++) {
                    const float p = (u == 0) ? pv[r].x : (u == 1) ? pv[r].y
                                  : (u == 2) ? pv[r].z : pv[r].w;
                    acc[r].x += p * vv.x;
                    acc[r].y += p * vv.y;
                    acc[r].z += p * vv.z;
                    acc[r].w += p * vv.w;
                }
            }
        }
    }

    #pragma unroll
    for (int r = 0; r < 8; r++) {
        const float inv = 1.f / l_i[r];
        float4 o = acc[r];
        o.x *= inv; o.y *= inv; o.z *= inv; o.w *= inv;
        const int row = q0 + warp * 8 + r;
        *(float4*)(out + (size_t)row * DIM + h * HEAD_DIM + lane * 4) = o;
    }
}

// ---------------------------------------------------------------------------
extern "C" void kernel_launch(void* const* d_in, const int* in_sizes, int n_in,
                              void* d_out, int out_size)
{
    (void)in_sizes; (void)n_in; (void)out_size;
    const float* x  = (const float*)d_in[0];
    const float* cs = (const float*)d_in[1];
    const float* sn = (const float*)d_in[2];
    const float* Wq = (const float*)d_in[3];
    const float* bq = (const float*)d_in[4];
    const float* Wk = (const float*)d_in[5];
    const float* bk = (const float*)d_in[6];
    const float* Wv = (const float*)d_in[7];
    const float* bv = (const float*)d_in[8];
    const float* gq = (const float*)d_in[9];
    const float* gk = (const float*)d_in[10];
    float* out = (float*)d_out;

    // Stage 1: QKV projections (mma.sync tf32, A hi/lo split)
    cudaFuncSetAttribute(qkv_mma_kernel, cudaFuncAttributeMaxDynamicSharedMemorySize,
                         QSMEM_BYTES);
    dim3 gg(DIM / 128, S_LEN / 128, 3);
    qkv_mma_kernel<<<gg, 256, QSMEM_BYTES>>>(x, Wq, bq, Wk, bk, Wv, bv);

    // Stage 2: RMSNorm + RoPE on q, k
    const int warps  = 2 * S_LEN * HEADS;
    const int thr    = 256;
    const int blocks = (warps * 32 + thr - 1) / thr;
    rms_rope_kernel<<<blocks, thr>>>(cs, sn, gq, gk);

    // Stage 3: attention
    cudaFuncSetAttribute(attn_kernel, cudaFuncAttributeMaxDynamicSharedMemorySize,
                         ATTN_SMEM_BYTES);
    dim3 ga(S_LEN / BQ, HEADS);
    attn_kernel<<<ga, ATTN_THREADS, ATTN_SMEM_BYTES>>>(out);
}

// round 7
// speedup vs baseline: 1.9012x; 1.2792x over previous
#include <cuda_runtime.h>
#include <math.h>
#include <stdint.h>

#define S_LEN    2048
#define DIM      3072
#define HEADS    24
#define HEAD_DIM 128

// Scratch (no cudaMalloc allowed): q, k, v post-projection
__device__ float g_q[S_LEN * DIM];
__device__ float g_k[S_LEN * DIM];
__device__ float g_v[S_LEN * DIM];

// ---- helpers -------------------------------------------------------------
__device__ __forceinline__ uint32_t tf32_rna(float x) {
    uint32_t r;
    asm("cvt.rna.tf32.f32 %0, %1;" : "=r"(r) : "f"(x));
    return r;
}
__device__ __forceinline__ void mma_tf32(float c[4], const uint32_t a[4], const uint32_t b[2]) {
    asm volatile(
        "mma.sync.aligned.m16n8k8.row.col.f32.tf32.tf32.f32 "
        "{%0,%1,%2,%3}, {%4,%5,%6,%7}, {%8,%9}, {%0,%1,%2,%3};"
        : "+f"(c[0]), "+f"(c[1]), "+f"(c[2]), "+f"(c[3])
        : "r"(a[0]), "r"(a[1]), "r"(a[2]), "r"(a[3]), "r"(b[0]), "r"(b[1]));
}

// ===========================================================================
// Stage 1: QKV projection via mma.sync tf32 (A = hi+lo split, B = tf32-rna).
// (unchanged from round 6 — validated: 1558us, tensor=48.9%)
// ===========================================================================
#define QA_STRIDE 36
#define QB_STRIDE 136
#define QA_FLOATS (128 * QA_STRIDE)
#define QB_FLOATS (32 * QB_STRIDE)
#define QBUF_FLOATS (2 * QA_FLOATS + QB_FLOATS)
#define QSMEM_BYTES (2 * QBUF_FLOATS * 4)
#define NCHUNK (DIM / 32)

__global__ __launch_bounds__(256, 1) void qkv_mma_kernel(
    const float* __restrict__ x,
    const float* __restrict__ Wq, const float* __restrict__ bq,
    const float* __restrict__ Wk, const float* __restrict__ bk,
    const float* __restrict__ Wv, const float* __restrict__ bv)
{
    extern __shared__ float smem[];
    const float* W; const float* bias; float* out;
    if (blockIdx.z == 0)      { W = Wq; bias = bq; out = g_q; }
    else if (blockIdx.z == 1) { W = Wk; bias = bk; out = g_k; }
    else                      { W = Wv; bias = bv; out = g_v; }

    const int tid  = threadIdx.x;
    const int wid  = tid >> 5;
    const int lane = tid & 31;
    const int g    = lane >> 2;
    const int tg   = lane & 3;
    const int wm   = wid >> 2;
    const int wn   = wid & 3;
    const int row0 = blockIdx.y * 128;
    const int col0 = blockIdx.x * 128;

    const int arow = tid >> 1;
    const int acol = (tid & 1) * 16;
    const int brow = tid >> 3;
    const int bcol = (tid & 7) * 16;

    const float* xA = x + (size_t)(row0 + arow) * DIM + acol;
    const float* wB = W + (size_t)brow * DIM + col0 + bcol;

    float acc[4][4][4];
    #pragma unroll
    for (int i = 0; i < 4; i++)
        #pragma unroll
        for (int j = 0; j < 4; j++)
            #pragma unroll
            for (int r = 0; r < 4; r++) acc[i][j][r] = 0.f;

    auto As_h = [&](int b) { return smem + (size_t)b * QBUF_FLOATS; };
    auto As_l = [&](int b) { return smem + (size_t)b * QBUF_FLOATS + QA_FLOATS; };
    auto Bs   = [&](int b) { return smem + (size_t)b * QBUF_FLOATS + 2 * QA_FLOATS; };

    {
        #pragma unroll
        for (int j = 0; j < 4; j++) {
            float4 v = *(const float4*)(xA + j * 4);
            uint4 h, l;
            h.x = tf32_rna(v.x); l.x = tf32_rna(v.x - __uint_as_float(h.x));
            h.y = tf32_rna(v.y); l.y = tf32_rna(v.y - __uint_as_float(h.y));
            h.z = tf32_rna(v.z); l.z = tf32_rna(v.z - __uint_as_float(h.z));
            h.w = tf32_rna(v.w); l.w = tf32_rna(v.w - __uint_as_float(h.w));
            *(uint4*)(As_h(0) + arow * QA_STRIDE + acol + j * 4) = h;
            *(uint4*)(As_l(0) + arow * QA_STRIDE + acol + j * 4) = l;
        }
        #pragma unroll
        for (int j = 0; j < 4; j++) {
            float4 v = *(const float4*)(wB + j * 4);
            uint4 h;
            h.x = tf32_rna(v.x); h.y = tf32_rna(v.y);
            h.z = tf32_rna(v.z); h.w = tf32_rna(v.w);
            *(uint4*)(Bs(0) + brow * QB_STRIDE + bcol + j * 4) = h;
        }
    }

    for (int c = 0; c < NCHUNK; c++) {
        __syncthreads();
        const int b = c & 1;
        const bool has_next = (c + 1) < NCHUNK;

        float4 av[4], bv[4];
        if (has_next) {
            const int kn = (c + 1) * 32;
            #pragma unroll
            for (int j = 0; j < 4; j++) av[j] = *(const float4*)(xA + kn + j * 4);
            #pragma unroll
            for (int j = 0; j < 4; j++) bv[j] = *(const float4*)(wB + (size_t)kn * DIM + j * 4);
        }

        const uint32_t* Ah = (const uint32_t*)As_h(b);
        const uint32_t* Al = (const uint32_t*)As_l(b);
        const uint32_t* Bp = (const uint32_t*)Bs(b);
        #pragma unroll
        for (int kk8 = 0; kk8 < 4; kk8++) {
            const int kk = kk8 * 8;
            uint32_t ah[4][4], al[4][4], bb[4][2];
            #pragma unroll
            for (int i = 0; i < 4; i++) {
                const int r = wm * 64 + i * 16 + g;
                ah[i][0] = Ah[(r)     * QA_STRIDE + kk + tg];
                ah[i][1] = Ah[(r + 8) * QA_STRIDE + kk + tg];
                ah[i][2] = Ah[(r)     * QA_STRIDE + kk + tg + 4];
                ah[i][3] = Ah[(r + 8) * QA_STRIDE + kk + tg + 4];
                al[i][0] = Al[(r)     * QA_STRIDE + kk + tg];
                al[i][1] = Al[(r + 8) * QA_STRIDE + kk + tg];
                al[i][2] = Al[(r)     * QA_STRIDE + kk + tg + 4];
                al[i][3] = Al[(r + 8) * QA_STRIDE + kk + tg + 4];
            }
            #pragma unroll
            for (int j = 0; j < 4; j++) {
                const int n = wn * 32 + j * 8 + g;
                bb[j][0] = Bp[(kk + tg)     * QB_STRIDE + n];
                bb[j][1] = Bp[(kk + tg + 4) * QB_STRIDE + n];
            }
            #pragma unroll
            for (int i = 0; i < 4; i++)
                #pragma unroll
                for (int j = 0; j < 4; j++) {
                    mma_tf32(acc[i][j], ah[i], bb[j]);
                    mma_tf32(acc[i][j], al[i], bb[j]);
                }
        }

        if (has_next) {
            const int nb = b ^ 1;
            #pragma unroll
            for (int j = 0; j < 4; j++) {
                uint4 h, l;
                h.x = tf32_rna(av[j].x); l.x = tf32_rna(av[j].x - __uint_as_float(h.x));
                h.y = tf32_rna(av[j].y); l.y = tf32_rna(av[j].y - __uint_as_float(h.y));
                h.z = tf32_rna(av[j].z); l.z = tf32_rna(av[j].z - __uint_as_float(h.z));
                h.w = tf32_rna(av[j].w); l.w = tf32_rna(av[j].w - __uint_as_float(h.w));
                *(uint4*)(As_h(nb) + arow * QA_STRIDE + acol + j * 4) = h;
                *(uint4*)(As_l(nb) + arow * QA_STRIDE + acol + j * 4) = l;
            }
            #pragma unroll
            for (int j = 0; j < 4; j++) {
                uint4 h;
                h.x = tf32_rna(bv[j].x); h.y = tf32_rna(bv[j].y);
                h.z = tf32_rna(bv[j].z); h.w = tf32_rna(bv[j].w);
                *(uint4*)(Bs(nb) + brow * QB_STRIDE + bcol + j * 4) = h;
            }
        }
    }

    #pragma unroll
    for (int j = 0; j < 4; j++) {
        const int n = col0 + wn * 32 + j * 8 + 2 * tg;
        const float2 bb = *(const float2*)(bias + n);
        #pragma unroll
        for (int i = 0; i < 4; i++) {
            const int r = row0 + wm * 64 + i * 16 + g;
            float2 o0 = make_float2(acc[i][j][0] + bb.x, acc[i][j][1] + bb.y);
            float2 o1 = make_float2(acc[i][j][2] + bb.x, acc[i][j][3] + bb.y);
            *(float2*)(out + (size_t)r * DIM + n)       = o0;
            *(float2*)(out + (size_t)(r + 8) * DIM + n) = o1;
        }
    }
}

// ---------------------------------------------------------------------------
// Stage 2: per-head RMSNorm + RoPE applied in place to g_q and g_k.
// ---------------------------------------------------------------------------
__global__ __launch_bounds__(256) void rms_rope_kernel(
    const float* __restrict__ cosb, const float* __restrict__ sinb,
    const float* __restrict__ gq, const float* __restrict__ gk)
{
    const int gw   = (blockIdx.x * blockDim.x + threadIdx.x) >> 5;
    const int lane = threadIdx.x & 31;
    const int rows = S_LEN * HEADS;
    if (gw >= 2 * rows) return;

    const int t  = (gw >= rows) ? 1 : 0;
    const int rr = t ? (gw - rows) : gw;
    const int s  = rr / HEADS;

    float* ptr = (t ? g_k : g_q) + (size_t)rr * HEAD_DIM;
    const float* g = t ? gk : gq;

    float4 vx = *(float4*)(ptr + lane * 4);
    float ss = vx.x * vx.x + vx.y * vx.y + vx.z * vx.z + vx.w * vx.w;
    #pragma unroll
    for (int o = 16; o > 0; o >>= 1) ss += __shfl_xor_sync(0xffffffffu, ss, o);
    const float rnorm = rsqrtf(ss * (1.0f / HEAD_DIM) + 1e-6f);

    float4 gg = *(const float4*)(g + lane * 4);
    vx.x *= rnorm * gg.x; vx.y *= rnorm * gg.y;
    vx.z *= rnorm * gg.z; vx.w *= rnorm * gg.w;

    float4 c  = *(const float4*)(cosb + (size_t)s * HEAD_DIM + lane * 4);
    float4 sn = *(const float4*)(sinb + (size_t)s * HEAD_DIM + lane * 4);
    float4 o;
    o.x = vx.x * c.x - vx.y * sn.x;
    o.y = vx.y * c.y + vx.x * sn.y;
    o.z = vx.z * c.z - vx.w * sn.z;
    o.w = vx.w * c.w + vx.z * sn.w;
    *(float4*)(ptr + lane * 4) = o;
}

// ===========================================================================
// Stage 3: flash attention on mma.sync tf32.
// CTA: 64 q-rows x 1 head, 8 warps = (wm 0-3 rowblock16, wh 0-1 col-half).
// S phase:  Q hi/lo split vs K plain tf32  (error = K rounding only)
// PV phase: P hi/lo split vs V plain tf32  (error = V rounding only)
// Smem strides chosen so every fragment LDS is bank-conflict-free:
//   Q 132 (A-type, ≡4 mod 32), K 132 (B via column index, ≡4), V 136 (B, ≡8),
//   P 68 (A-type, ≡4).
// ===========================================================================
#define AT_THREADS 256
// u32 layout offsets
#define AT_QH 0
#define AT_QL (AT_QH + 64*132)
#define AT_KS (AT_QL + 64*132)
#define AT_VS (AT_KS + 64*132)
#define AT_PH (AT_VS + 64*136)
#define AT_PL (AT_PH + 64*68)
#define AT_RMAX (AT_PL + 64*68)
#define AT_RSUM (AT_RMAX + 128)
#define AT_TOTAL (AT_RSUM + 128)
#define AT_SMEM_BYTES (AT_TOTAL * 4)

__global__ __launch_bounds__(AT_THREADS, 1) void attn_mma_kernel(float* __restrict__ out)
{
    extern __shared__ uint32_t smu[];
    uint32_t* Qh = smu + AT_QH;
    uint32_t* Ql = smu + AT_QL;
    uint32_t* Ks = smu + AT_KS;
    uint32_t* Vs = smu + AT_VS;
    uint32_t* Ph = smu + AT_PH;
    uint32_t* Pl = smu + AT_PL;
    float* Rmax = (float*)(smu + AT_RMAX);
    float* Rsum = (float*)(smu + AT_RSUM);

    const int h    = blockIdx.y;
    const int q0   = blockIdx.x * 64;
    const int tid  = threadIdx.x;
    const int wid  = tid >> 5;
    const int lane = tid & 31;
    const int g    = lane >> 2;
    const int tg   = lane & 3;
    const int wm   = wid & 3;      // q row-block (16 rows)
    const int wh   = wid >> 2;     // column half
    const int ri0  = wm * 16 + g;
    const int ri1  = ri0 + 8;

    const float scale = 0.08838834764831845f;   // 1/sqrt(128)

    // ---- load Q tile (scaled), split hi/lo ----
    for (int i = tid; i < 64 * 32; i += AT_THREADS) {
        const int r  = i >> 5;
        const int c4 = (i & 31) * 4;
        float4 v = *(const float4*)(g_q + ((size_t)(q0 + r) * HEADS + h) * HEAD_DIM + c4);
        v.x *= scale; v.y *= scale; v.z *= scale; v.w *= scale;
        uint4 hh, ll;
        hh.x = tf32_rna(v.x); ll.x = tf32_rna(v.x - __uint_as_float(hh.x));
        hh.y = tf32_rna(v.y); ll.y = tf32_rna(v.y - __uint_as_float(hh.y));
        hh.z = tf32_rna(v.z); ll.z = tf32_rna(v.z - __uint_as_float(hh.z));
        hh.w = tf32_rna(v.w); ll.w = tf32_rna(v.w - __uint_as_float(hh.w));
        *(uint4*)(Qh + r * 132 + c4) = hh;
        *(uint4*)(Ql + r * 132 + c4) = ll;
    }

    float m0 = -INFINITY, m1 = -INFINITY, l0 = 0.f, l1 = 0.f;
    float o[8][4];
    #pragma unroll
    for (int j = 0; j < 8; j++)
        #pragma unroll
        for (int r = 0; r < 4; r++) o[j][r] = 0.f;

    for (int kv0 = 0; kv0 < S_LEN; kv0 += 64) {
        __syncthreads();   // previous tile fully consumed
        // ---- load K, V tiles (tf32) ----
        for (int i = tid; i < 64 * 32; i += AT_THREADS) {
            const int r  = i >> 5;
            const int c4 = (i & 31) * 4;
            float4 kv4 = *(const float4*)(g_k + ((size_t)(kv0 + r) * HEADS + h) * HEAD_DIM + c4);
            uint4 t;
            t.x = tf32_rna(kv4.x); t.y = tf32_rna(kv4.y);
            t.z = tf32_rna(kv4.z); t.w = tf32_rna(kv4.w);
            *(uint4*)(Ks + r * 132 + c4) = t;
            float4 vv4 = *(const float4*)(g_v + ((size_t)(kv0 + r) * HEADS + h) * HEAD_DIM + c4);
            uint4 u;
            u.x = tf32_rna(vv4.x); u.y = tf32_rna(vv4.y);
            u.z = tf32_rna(vv4.z); u.w = tf32_rna(vv4.w);
            *(uint4*)(Vs + r * 136 + c4) = u;
        }
        __syncthreads();

        // ---- S = Q K^T on tensor cores ----
        float s[4][4];
        #pragma unroll
        for (int j = 0; j < 4; j++)
            #pragma unroll
            for (int r = 0; r < 4; r++) s[j][r] = 0.f;

        #pragma unroll
        for (int kk8 = 0; kk8 < 16; kk8++) {
            const int kk = kk8 * 8;
            uint32_t ah[4], al[4];
            ah[0] = Qh[ri0 * 132 + kk + tg];
            ah[1] = Qh[ri1 * 132 + kk + tg];
            ah[2] = Qh[ri0 * 132 + kk + tg + 4];
            ah[3] = Qh[ri1 * 132 + kk + tg + 4];
            al[0] = Ql[ri0 * 132 + kk + tg];
            al[1] = Ql[ri1 * 132 + kk + tg];
            al[2] = Ql[ri0 * 132 + kk + tg + 4];
            al[3] = Ql[ri1 * 132 + kk + tg + 4];
            #pragma unroll
            for (int j = 0; j < 4; j++) {
                const int nv = wh * 32 + j * 8 + g;
                uint32_t bb[2];
                bb[0] = Ks[nv * 132 + kk + tg];
                bb[1] = Ks[nv * 132 + kk + tg + 4];
                mma_tf32(s[j], ah, bb);
                mma_tf32(s[j], al, bb);
            }
        }

        // ---- row max (quad reduce + cross-warp via smem) ----
        float mx0 = fmaxf(fmaxf(s[0][0], s[0][1]), fmaxf(s[1][0], s[1][1]));
        mx0 = fmaxf(mx0, fmaxf(fmaxf(s[2][0], s[2][1]), fmaxf(s[3][0], s[3][1])));
        float mx1 = fmaxf(fmaxf(s[0][2], s[0][3]), fmaxf(s[1][2], s[1][3]));
        mx1 = fmaxf(mx1, fmaxf(fmaxf(s[2][2], s[2][3]), fmaxf(s[3][2], s[3][3])));
        mx0 = fmaxf(mx0, __shfl_xor_sync(0xffffffffu, mx0, 1));
        mx0 = fmaxf(mx0, __shfl_xor_sync(0xffffffffu, mx0, 2));
        mx1 = fmaxf(mx1, __shfl_xor_sync(0xffffffffu, mx1, 1));
        mx1 = fmaxf(mx1, __shfl_xor_sync(0xffffffffu, mx1, 2));
        if (tg == 0) {
            Rmax[wh * 64 + ri0] = mx0;
            Rmax[wh * 64 + ri1] = mx1;
        }
        __syncthreads();
        const float mt0 = fmaxf(Rmax[ri0], Rmax[64 + ri0]);
        const float mt1 = fmaxf(Rmax[ri1], Rmax[64 + ri1]);
        const float mn0 = fmaxf(m0, mt0);
        const float mn1 = fmaxf(m1, mt1);
        const float alpha0 = __expf(m0 - mn0);
        const float alpha1 = __expf(m1 - mn1);

        // ---- p = exp(s - m), stage hi/lo P, partial row sums ----
        float sum0 = 0.f, sum1 = 0.f;
        #pragma unroll
        for (int j = 0; j < 4; j++) {
            const int col = wh * 32 + j * 8 + 2 * tg;
            const float p0 = __expf(s[j][0] - mn0);
            const float p1 = __expf(s[j][1] - mn0);
            const float p2 = __expf(s[j][2] - mn1);
            const float p3 = __expf(s[j][3] - mn1);
            sum0 += p0 + p1;
            sum1 += p2 + p3;
            uint32_t hv, lv;
            hv = tf32_rna(p0); lv = tf32_rna(p0 - __uint_as_float(hv));
            Ph[ri0 * 68 + col] = hv; Pl[ri0 * 68 + col] = lv;
            hv = tf32_rna(p1); lv = tf32_rna(p1 - __uint_as_float(hv));
            Ph[ri0 * 68 + col + 1] = hv; Pl[ri0 * 68 + col + 1] = lv;
            hv = tf32_rna(p2); lv = tf32_rna(p2 - __uint_as_float(hv));
            Ph[ri1 * 68 + col] = hv; Pl[ri1 * 68 + col] = lv;
            hv = tf32_rna(p3); lv = tf32_rna(p3 - __uint_as_float(hv));
            Ph[ri1 * 68 + col + 1] = hv; Pl[ri1 * 68 + col + 1] = lv;
        }
        sum0 += __shfl_xor_sync(0xffffffffu, sum0, 1);
        sum0 += __shfl_xor_sync(0xffffffffu, sum0, 2);
        sum1 += __shfl_xor_sync(0xffffffffu, sum1, 1);
        sum1 += __shfl_xor_sync(0xffffffffu, sum1, 2);
        if (tg == 0) {
            Rsum[wh * 64 + ri0] = sum0;
            Rsum[wh * 64 + ri1] = sum1;
        }
        __syncthreads();
        l0 = l0 * alpha0 + Rsum[ri0] + Rsum[64 + ri0];
        l1 = l1 * alpha1 + Rsum[ri1] + Rsum[64 + ri1];
        m0 = mn0; m1 = mn1;

        // ---- rescale accumulators ----
        #pragma unroll
        for (int j = 0; j < 8; j++) {
            o[j][0] *= alpha0; o[j][1] *= alpha0;
            o[j][2] *= alpha1; o[j][3] *= alpha1;
        }

        // ---- O += P V on tensor cores ----
        #pragma unroll
        for (int kk8 = 0; kk8 < 8; kk8++) {
            const int kk = kk8 * 8;
            uint32_t ah[4], al[4];
            ah[0] = Ph[ri0 * 68 + kk + tg];
            ah[1] = Ph[ri1 * 68 + kk + tg];
            ah[2] = Ph[ri0 * 68 + kk + tg + 4];
            ah[3] = Ph[ri1 * 68 + kk + tg + 4];
            al[0] = Pl[ri0 * 68 + kk + tg];
            al[1] = Pl[ri1 * 68 + kk + tg];
            al[2] = Pl[ri0 * 68 + kk + tg + 4];
            al[3] = Pl[ri1 * 68 + kk + tg + 4];
            #pragma unroll
            for (int j = 0; j < 8; j++) {
                const int nd = wh * 64 + j * 8 + g;
                uint32_t bb[2];
                bb[0] = Vs[(kk + tg)     * 136 + nd];
                bb[1] = Vs[(kk + tg + 4) * 136 + nd];
                mma_tf32(o[j], ah, bb);
                mma_tf32(o[j], al, bb);
            }
        }
    }

    // ---- epilogue ----
    const float inv0 = 1.f / l0;
    const float inv1 = 1.f / l1;
    #pragma unroll
    for (int j = 0; j < 8; j++) {
        const int d = h * HEAD_DIM + wh * 64 + j * 8 + 2 * tg;
        *(float2*)(out + (size_t)(q0 + ri0) * DIM + d) =
            make_float2(o[j][0] * inv0, o[j][1] * inv0);
        *(float2*)(out + (size_t)(q0 + ri1) * DIM + d) =
            make_float2(o[j][2] * inv1, o[j][3] * inv1);
    }
}

// ---------------------------------------------------------------------------
extern "C" void kernel_launch(void* const* d_in, const int* in_sizes, int n_in,
                              void* d_out, int out_size)
{
    (void)in_sizes; (void)n_in; (void)out_size;
    const float* x  = (const float*)d_in[0];
    const float* cs = (const float*)d_in[1];
    const float* sn = (const float*)d_in[2];
    const float* Wq = (const float*)d_in[3];
    const float* bq = (const float*)d_in[4];
    const float* Wk = (const float*)d_in[5];
    const float* bk = (const float*)d_in[6];
    const float* Wv = (const float*)d_in[7];
    const float* bv = (const float*)d_in[8];
    const float* gq = (const float*)d_in[9];
    const float* gk = (const float*)d_in[10];
    float* out = (float*)d_out;

    // Stage 1: QKV projections (mma.sync tf32, A hi/lo split)
    cudaFuncSetAttribute(qkv_mma_kernel, cudaFuncAttributeMaxDynamicSharedMemorySize,
                         QSMEM_BYTES);
    dim3 gg(DIM / 128, S_LEN / 128, 3);
    qkv_mma_kernel<<<gg, 256, QSMEM_BYTES>>>(x, Wq, bq, Wk, bk, Wv, bv);

    // Stage 2: RMSNorm + RoPE on q, k
    const int warps  = 2 * S_LEN * HEADS;
    const int thr    = 256;
    const int blocks = (warps * 32 + thr - 1) / thr;
    rms_rope_kernel<<<blocks, thr>>>(cs, sn, gq, gk);

    // Stage 3: attention (mma.sync tf32)
    cudaFuncSetAttribute(attn_mma_kernel, cudaFuncAttributeMaxDynamicSharedMemorySize,
                         AT_SMEM_BYTES);
    dim3 ga(S_LEN / 64, HEADS);
    attn_mma_kernel<<<ga, AT_THREADS, AT_SMEM_BYTES>>>(out);
}